// round 3
// baseline (speedup 1.0000x reference)
#include <cuda_runtime.h>
#include <cstdint>

#define TSTEPS  1024
#define FEAT    64
#define UNITS   256
#define FOURU   1024
#define KDIM    320      // 64 (W rows) + 256 (Uh rows)
#define KQLEN   80       // K rows per k-quarter warp-lane group
#define NCOLS   128      // gate-columns per CTA: 32 units x 4 gates
#define ASTR    36       // padded floats per a_t row
#define CLUSTER 8
#define THREADS 512
#define BB      32       // batch rows per cluster
#define NCLUST  16

// ---------- packed f32x2 helpers ----------
__device__ __forceinline__ unsigned long long pk2(float lo, float hi) {
    unsigned long long r;
    asm("mov.b64 %0, {%1, %2};" : "=l"(r) : "f"(lo), "f"(hi));
    return r;
}
__device__ __forceinline__ void fma2(unsigned long long& d,
                                     unsigned long long a,
                                     unsigned long long b) {
    asm("fma.rn.f32x2 %0, %1, %2, %0;" : "+l"(d) : "l"(a), "l"(b));
}
__device__ __forceinline__ float2 up2(unsigned long long v) {
    float2 r;
    asm("mov.b64 {%0, %1}, %2;" : "=f"(r.x), "=f"(r.y) : "l"(v));
    return r;
}
// butterfly partial-sum combine across kq lanes (xor mask m), packed add
__device__ __forceinline__ unsigned long long xadd(unsigned long long v, int m) {
    uint32_t lo, hi;
    asm("mov.b64 {%0,%1}, %2;" : "=r"(lo), "=r"(hi) : "l"(v));
    lo = __shfl_xor_sync(0xffffffffu, lo, m);
    hi = __shfl_xor_sync(0xffffffffu, hi, m);
    unsigned long long o;
    asm("mov.b64 %0, {%1,%2};" : "=l"(o) : "r"(lo), "r"(hi));
    asm("add.rn.f32x2 %0, %0, %1;" : "+l"(v) : "l"(o));
    return v;
}

__device__ __forceinline__ float fsig(float x) {
    return __fdividef(1.0f, 1.0f + __expf(-x));
}
__device__ __forceinline__ float ftanh(float x) {
    return fmaf(2.0f, fsig(2.0f * x), -1.0f);
}

// Persistent 8-CTA-cluster LSTM. CTA owns 32 units (128 gate cols), weights in
// SMEM. 16 warps: warp = (bq<<2)|ugq covers batch-group bq (8 batches) x
// unit-group ugq (8 units); lane = kq*8+u8 covers K-quarter kq of unit u8.
// Partial z reduced via 2 shfl_xor rounds; lane kq finishes gates for its 2
// batches; h broadcast to 8 CTAs via DSMEM.
extern "C" __global__ void __launch_bounds__(THREADS, 1) __cluster_dims__(CLUSTER, 1, 1)
lstm_attn_kernel(const float* __restrict__ x,  const float* __restrict__ W,
                 const float* __restrict__ Uh, const float* __restrict__ bias,
                 const float* __restrict__ dw, const float* __restrict__ db,
                 float* __restrict__ out)
{
    extern __shared__ float smem[];
    float* Uc  = smem;                    // [KDIM][NCOLS]   163840 B
    float* at  = smem + KDIM * NCOLS;     // [KDIM][ASTR]     46080 B  (a = [x_t ; h])
    float* bsm = at + KDIM * ASTR;        // [NCOLS]            512 B

    const int tid = threadIdx.x;
    uint32_t rank, cid;
    asm("mov.u32 %0, %%cluster_ctarank;" : "=r"(rank));
    asm("mov.u32 %0, %%clusterid.x;"     : "=r"(cid));

    // ---- one-time: load weight slice (col = unit*4 + gate) ----
    for (int idx = tid; idx < KDIM * NCOLS; idx += THREADS) {
        const int k    = idx >> 7;
        const int c    = idx & 127;
        const int gcol = (c & 3) * UNITS + (int)rank * 32 + (c >> 2);
        Uc[k * NCOLS + c] = (k < FEAT) ? W[(size_t)k * FOURU + gcol]
                                       : Uh[(size_t)(k - FEAT) * FOURU + gcol];
    }
    if (tid < NCOLS)
        bsm[tid] = bias[(tid & 3) * UNITS + (int)rank * 32 + (tid >> 2)];
    // zero the h region of a (rows 64..319)
    for (int i = tid; i < UNITS * ASTR; i += THREADS)
        at[FEAT * ASTR + i] = 0.0f;
    __syncthreads();

    const int wid  = tid >> 5;
    const int lane = tid & 31;
    const int ugq  = wid & 3;       // unit group (8 units)
    const int bq   = wid >> 2;      // batch group (8 batches)
    const int kq   = lane >> 3;     // K quarter
    const int u8   = lane & 7;      // unit within group
    const int unit = ugq * 8 + u8;  // 0..31

    float b4[4];
    #pragma unroll
    for (int g = 0; g < 4; g++) b4[g] = bsm[unit * 4 + g];

    const float* xb = x + (size_t)cid * BB * TSTEPS * FEAT;
    const int xb_b  = tid >> 4;     // batch this thread stages (0..31)
    const int xb_fq = tid & 15;     // float4 index within row

    float cst0 = 0.0f, cst1 = 0.0f;    // c state for my 2 batches

    // shared::cluster u32 address of my h destination (row=unit, col=2 batches)
    uint32_t at_u32;
    asm("{ .reg .u64 t0; cvta.to.shared.u64 t0, %1; cvt.u32.u64 %0, t0; }"
        : "=r"(at_u32) : "l"(at));
    const uint32_t hdst = at_u32 +
        (uint32_t)(((FEAT + (int)rank * 32 + unit) * ASTR + bq * 8 + kq * 2) * 4);

    const float* ucp = Uc + unit * 4 + kq * KQLEN * NCOLS;
    const float* ap  = at + bq * 8  + kq * KQLEN * ASTR;

    for (int t = 0; t < TSTEPS; t++) {
        // ---- stage x_t into a rows [0,64): a[f][b] = x[b,t,f] ----
        {
            const float4 v = *reinterpret_cast<const float4*>(
                xb + ((size_t)xb_b * TSTEPS + t) * FEAT + xb_fq * 4);
            const int r0 = xb_fq * 4;
            at[(r0 + 0) * ASTR + xb_b] = v.x;
            at[(r0 + 1) * ASTR + xb_b] = v.y;
            at[(r0 + 2) * ASTR + xb_b] = v.z;
            at[(r0 + 3) * ASTR + xb_b] = v.w;
        }
        __syncthreads();

        // ---- partial z over my K-quarter: 8 batches x 4 gates ----
        unsigned long long acc[4][4];
        #pragma unroll
        for (int p = 0; p < 4; p++)
            #pragma unroll
            for (int g = 0; g < 4; g++)
                acc[p][g] = 0ull;

        #pragma unroll 4
        for (int kk = 0; kk < KQLEN; kk++) {
            const float4 u4 = *reinterpret_cast<const float4*>(ucp + kk * NCOLS);
            const float4 a0 = *reinterpret_cast<const float4*>(ap + kk * ASTR);
            const float4 a1 = *reinterpret_cast<const float4*>(ap + kk * ASTR + 4);
            unsigned long long ug[4] = { pk2(u4.x, u4.x), pk2(u4.y, u4.y),
                                         pk2(u4.z, u4.z), pk2(u4.w, u4.w) };
            unsigned long long apair[4] = { pk2(a0.x, a0.y), pk2(a0.z, a0.w),
                                            pk2(a1.x, a1.y), pk2(a1.z, a1.w) };
            #pragma unroll
            for (int p = 0; p < 4; p++)
                #pragma unroll
                for (int g = 0; g < 4; g++)
                    fma2(acc[p][g], apair[p], ug[g]);
        }

        // all cluster CTAs finished READING a; safe to overwrite h after wait
        asm volatile("barrier.cluster.arrive.aligned;" ::: "memory");

        // ---- reduce K-quarters across lanes (register-only) ----
        #pragma unroll
        for (int p = 0; p < 4; p++)
            #pragma unroll
            for (int g = 0; g < 4; g++) {
                acc[p][g] = xadd(acc[p][g], 8);
                acc[p][g] = xadd(acc[p][g], 16);
            }

        // ---- gates for my 2 batches (p == kq) ----
        const float2 zi = up2(acc[kq][0]);
        const float2 zf = up2(acc[kq][1]);
        const float2 zg = up2(acc[kq][2]);
        const float2 zo = up2(acc[kq][3]);
        float h0, h1;
        {
            const float ig = fsig(zi.x + b4[0]), fg = fsig(zf.x + b4[1]);
            const float gg = ftanh(zg.x + b4[2]), og = fsig(zo.x + b4[3]);
            cst0 = fmaf(fg, cst0, ig * gg);
            h0   = og * ftanh(cst0);
        }
        {
            const float ig = fsig(zi.y + b4[0]), fg = fsig(zf.y + b4[1]);
            const float gg = ftanh(zg.y + b4[2]), og = fsig(zo.y + b4[3]);
            cst1 = fmaf(fg, cst1, ig * gg);
            h1   = og * ftanh(cst1);
        }
        const unsigned long long hv = pk2(h0, h1);

        asm volatile("barrier.cluster.wait.aligned;" ::: "memory");

        // ---- broadcast my h pair (unit, 2 batches) to all 8 CTAs ----
        #pragma unroll
        for (int r = 0; r < CLUSTER; r++) {
            uint32_t ra;
            asm("mapa.shared::cluster.u32 %0, %1, %2;" : "=r"(ra) : "r"(hdst), "r"(r));
            asm volatile("st.shared::cluster.b64 [%0], %1;" ::
                         "r"(ra), "l"(hv) : "memory");
        }

        // h writes must be visible cluster-wide before next step's GEMM
        asm volatile("barrier.cluster.arrive.aligned;" ::: "memory");
        asm volatile("barrier.cluster.wait.aligned;"   ::: "memory");
    }

    // ---- epilogue: out[b, t] = sigmoid(h_T[b] . dw + db) for all t ----
    // (softmax over size-1 axis == 1 -> attn row == h_T)
    {
        const int bl = (int)rank * 4 + (wid & 3);   // batch row (4 per CTA)
        float s = 0.0f;
        for (int u = lane; u < UNITS; u += 32)
            s += at[(FEAT + u) * ASTR + bl] * dw[u];
        #pragma unroll
        for (int o = 16; o > 0; o >>= 1)
            s += __shfl_xor_sync(0xffffffffu, s, o);
        const float val = fsig(s + db[0]);
        // 4 warps share each batch; warp-quarter (wid>>2) covers 256 t's
        float* op = out + ((size_t)cid * BB + bl) * TSTEPS + (wid >> 2) * 256;
        for (int i = lane; i < 256; i += 32)
            op[i] = val;
    }
}

extern "C" void kernel_launch(void* const* d_in, const int* in_sizes, int n_in,
                              void* d_out, int out_size)
{
    const float* x  = (const float*)d_in[0];
    const float* W  = (const float*)d_in[1];
    const float* Uh = (const float*)d_in[2];
    const float* b  = (const float*)d_in[3];
    const float* dw = (const float*)d_in[4];
    const float* db = (const float*)d_in[5];
    float* out = (float*)d_out;

    const size_t smem = (size_t)(KDIM * NCOLS + KDIM * ASTR + NCOLS) * sizeof(float);
    cudaFuncSetAttribute(lstm_attn_kernel,
                         cudaFuncAttributeMaxDynamicSharedMemorySize, (int)smem);
    lstm_attn_kernel<<<NCLUST * CLUSTER, THREADS, smem>>>(x, W, Uh, b, dw, db, out);
}